// round 2
// baseline (speedup 1.0000x reference)
#include <cuda_runtime.h>
#include <math.h>

#define B 16
#define N 32
#define C 512
#define FEAT 224

#define HW0 784
#define HW1 196
#define HW2 49
#define OUT_ROW (C*(HW0+HW1+HW2))
#define OUT_OFF1 (C*HW0)         // 401408
#define OUT_OFF2 (C*(HW0+HW1))   // 501760

// ---------------- scratch (no allocations allowed) ----------------
__device__ float g_att0[B * HW0];
__device__ float g_att1[B * HW1];
__device__ float g_att2[B * HW2];
__device__ float g_logits[3 * B * C];
__device__ float g_weights[3 * B * C];

// ---------------- K1: conf map + sigmoid + 3-level avgpool --------------
// grid = B blocks, 784 threads. Thread t owns one 8x8 pixel tile.
// Uses 32-bit row/col box masks: pixel value = sum of confs over set bits of
// (rowmask[y] & colmask[x]). Expected set-bit count ~1.3, vs 32-iteration loop.
__global__ void conf_att_kernel(const float* __restrict__ confs,
                                const float* __restrict__ boxes) {
    int b = blockIdx.x;
    __shared__ float sconf[N];
    __shared__ int sbx[N * 4];
    __shared__ unsigned rowm[FEAT], colm[FEAT];
    __shared__ float sum28[HW0];

    int t = threadIdx.x;
    if (t < N * 4) sbx[t] = (int)floorf(boxes[b * N * 4 + t] * (float)FEAT);
    if (t < N) sconf[t] = confs[b * N + t];
    __syncthreads();

    if (t < FEAT) {
        unsigned rm = 0, cm = 0;
#pragma unroll
        for (int n = 0; n < N; n++) {
            int x1 = sbx[4 * n], y1 = sbx[4 * n + 1];
            int x2 = sbx[4 * n + 2], y2 = sbx[4 * n + 3];
            rm |= (unsigned)(t >= y1 && t < y2) << n;
            cm |= (unsigned)(t >= x1 && t < x2) << n;
        }
        rowm[t] = rm;
        colm[t] = cm;
    }
    __syncthreads();

    int cy = t / 28, cx = t % 28;
    float tsum = 0.f;
    for (int ry = 0; ry < 8; ry++) {
        unsigned rm = rowm[cy * 8 + ry];
#pragma unroll
        for (int rx = 0; rx < 8; rx++) {
            unsigned m = rm & colm[cx * 8 + rx];
            float v = 0.f;
            while (m) {
                int i = __ffs(m) - 1;
                v += sconf[i];
                m &= m - 1;
            }
            tsum += 1.f / (1.f + __expf(-v));
        }
    }
    sum28[t] = tsum;
    g_att0[b * HW0 + t] = tsum * (1.f / 64.f);
    __syncthreads();

    if (t < HW1) {
        int ay = t / 14, ax = t % 14;
        float s = sum28[(2 * ay) * 28 + 2 * ax] + sum28[(2 * ay) * 28 + 2 * ax + 1] +
                  sum28[(2 * ay + 1) * 28 + 2 * ax] + sum28[(2 * ay + 1) * 28 + 2 * ax + 1];
        g_att1[b * HW1 + t] = s * (1.f / 256.f);
    }
    if (t < HW2) {
        int ay = t / 7, ax = t % 7;
        float s = 0.f;
#pragma unroll
        for (int i = 0; i < 4; i++)
#pragma unroll
            for (int j = 0; j < 4; j++)
                s += sum28[(4 * ay + i) * 28 + 4 * ax + j];
        g_att2[b * HW2 + t] = s * (1.f / 1024.f);
    }
}

// ---------------- K2: logits[l][b][c] = dot(feat[b,c,:], att[b,:]) ------
// grid = (C/8, B, 3), 256 threads = 8 warps; each warp does one c.
__global__ void logits_kernel(const float* __restrict__ f0,
                              const float* __restrict__ f1,
                              const float* __restrict__ f2) {
    int l = blockIdx.z, b = blockIdx.y;
    __shared__ __align__(16) float satt[HW0];

    int warp = threadIdx.x >> 5, lane = threadIdx.x & 31;
    int c = blockIdx.x * 8 + warp;
    float acc = 0.f;

    if (l == 0) {
        for (int i = threadIdx.x; i < HW0; i += 256) satt[i] = g_att0[b * HW0 + i];
        __syncthreads();
        const float4* fp = (const float4*)(f0 + ((size_t)(b * C + c)) * HW0);
        const float4* ap = (const float4*)satt;
#pragma unroll
        for (int k = 0; k < 7; k++) {
            int i = lane + 32 * k;
            if (i < HW0 / 4) {
                float4 v = fp[i], a = ap[i];
                acc = fmaf(v.x, a.x, acc);
                acc = fmaf(v.y, a.y, acc);
                acc = fmaf(v.z, a.z, acc);
                acc = fmaf(v.w, a.w, acc);
            }
        }
    } else if (l == 1) {
        for (int i = threadIdx.x; i < HW1; i += 256) satt[i] = g_att1[b * HW1 + i];
        __syncthreads();
        const float4* fp = (const float4*)(f1 + ((size_t)(b * C + c)) * HW1);
        const float4* ap = (const float4*)satt;
#pragma unroll
        for (int k = 0; k < 2; k++) {
            int i = lane + 32 * k;
            if (i < HW1 / 4) {
                float4 v = fp[i], a = ap[i];
                acc = fmaf(v.x, a.x, acc);
                acc = fmaf(v.y, a.y, acc);
                acc = fmaf(v.z, a.z, acc);
                acc = fmaf(v.w, a.w, acc);
            }
        }
    } else {
        for (int i = threadIdx.x; i < HW2; i += 256) satt[i] = g_att2[b * HW2 + i];
        __syncthreads();
        const float* fp = f2 + ((size_t)(b * C + c)) * HW2;
#pragma unroll
        for (int k = 0; k < 2; k++) {
            int i = lane + 32 * k;
            if (i < HW2) acc = fmaf(fp[i], satt[i], acc);
        }
    }

#pragma unroll
    for (int o = 16; o > 0; o >>= 1) acc += __shfl_xor_sync(0xffffffffu, acc, o);
    if (lane == 0) g_logits[(l * B + b) * C + c] = acc;
}

// ---------------- K3: softmax over C per (level, b) ----------------
__global__ void softmax_kernel() {
    int lb = blockIdx.x;
    int t = threadIdx.x;
    float x = g_logits[lb * C + t];

    __shared__ float red[16];
    __shared__ float smax, ssum;

    float m = x;
#pragma unroll
    for (int o = 16; o > 0; o >>= 1) m = fmaxf(m, __shfl_xor_sync(0xffffffffu, m, o));
    if ((t & 31) == 0) red[t >> 5] = m;
    __syncthreads();
    if (t == 0) {
        float mm = red[0];
#pragma unroll
        for (int i = 1; i < 16; i++) mm = fmaxf(mm, red[i]);
        smax = mm;
    }
    __syncthreads();

    float e = __expf(x - smax);
    float s = e;
#pragma unroll
    for (int o = 16; o > 0; o >>= 1) s += __shfl_xor_sync(0xffffffffu, s, o);
    if ((t & 31) == 0) red[t >> 5] = s;
    __syncthreads();
    if (t == 0) {
        float ss = 0.f;
#pragma unroll
        for (int i = 0; i < 16; i++) ss += red[i];
        ssum = ss;
    }
    __syncthreads();

    g_weights[lb * C + t] = e / ssum;
}

// ---------------- K4: out = feat * w, warp-per-(b,c)-row, all 3 levels ----
// grid = (B*C/8, 3), 256 threads = 8 warps. Each warp scales one row.
__global__ void scale_kernel(const float* __restrict__ f0,
                             const float* __restrict__ f1,
                             const float* __restrict__ f2,
                             float* __restrict__ out) {
    int level = blockIdx.y;
    int warp = threadIdx.x >> 5, lane = threadIdx.x & 31;
    int row = blockIdx.x * 8 + warp;          // 0 .. B*C-1
    int b = row >> 9, c = row & (C - 1);
    float w = g_weights[(level * B + b) * C + c];

    if (level == 0) {
        const float4* src = (const float4*)(f0 + (size_t)row * HW0);
        float4* dst = (float4*)(out + (size_t)b * OUT_ROW + (size_t)c * HW0);
#pragma unroll
        for (int k = 0; k < 7; k++) {
            int i = lane + 32 * k;
            if (i < HW0 / 4) {
                float4 v = src[i];
                v.x *= w; v.y *= w; v.z *= w; v.w *= w;
                dst[i] = v;
            }
        }
    } else if (level == 1) {
        const float4* src = (const float4*)(f1 + (size_t)row * HW1);
        float4* dst = (float4*)(out + (size_t)b * OUT_ROW + OUT_OFF1 + (size_t)c * HW1);
#pragma unroll
        for (int k = 0; k < 2; k++) {
            int i = lane + 32 * k;
            if (i < HW1 / 4) {
                float4 v = src[i];
                v.x *= w; v.y *= w; v.z *= w; v.w *= w;
                dst[i] = v;
            }
        }
    } else {
        const float* src = f2 + (size_t)row * HW2;
        float* dst = out + (size_t)b * OUT_ROW + OUT_OFF2 + (size_t)c * HW2;
#pragma unroll
        for (int k = 0; k < 2; k++) {
            int i = lane + 32 * k;
            if (i < HW2) dst[i] = src[i] * w;
        }
    }
}

extern "C" void kernel_launch(void* const* d_in, const int* in_sizes, int n_in,
                              void* d_out, int out_size) {
    const float* confs = (const float*)d_in[0];
    const float* boxes = (const float*)d_in[1];
    const float* f0 = (const float*)d_in[2];
    const float* f1 = (const float*)d_in[3];
    const float* f2 = (const float*)d_in[4];
    float* out = (float*)d_out;

    conf_att_kernel<<<B, HW0>>>(confs, boxes);
    logits_kernel<<<dim3(C / 8, B, 3), 256>>>(f0, f1, f2);
    softmax_kernel<<<3 * B, C>>>();
    scale_kernel<<<dim3(B * C / 8, 3), 256>>>(f0, f1, f2, out);
}

// round 3
// speedup vs baseline: 1.1066x; 1.1066x over previous
#include <cuda_runtime.h>
#include <math.h>

#define B 16
#define N 32
#define C 512
#define FEAT 224

#define HW0 784
#define HW1 196
#define HW2 49
#define OUT_ROW (C*(HW0+HW1+HW2))
#define OUT_OFF1 (C*HW0)         // 401408
#define OUT_OFF2 (C*(HW0+HW1))   // 501760

// ---------------- scratch (no allocations allowed) ----------------
__device__ float g_att0[B * HW0];
__device__ float g_att1[B * HW1];
__device__ float g_att2[B * HW2];
__device__ float g_logits[3 * B * C];

// ---------------- K1: conf map + sigmoid + 3-level avgpool --------------
// grid = (7, B): blockIdx.x = level-2 row band (32 pixel rows), blockIdx.y = b.
// 128 threads; threads 0..111 each own one 8x8 pixel tile (4 tile-rows x 28).
// Pixel value = sum of confs over set bits of rowmask[y] & colmask[x].
__global__ void conf_att_kernel(const float* __restrict__ confs,
                                const float* __restrict__ boxes) {
    int b = blockIdx.y;
    int r2 = blockIdx.x;              // 0..6
    __shared__ float sconf[N];
    __shared__ int sbx[N * 4];
    __shared__ unsigned rowm[32], colm[FEAT];
    __shared__ float sum28[4 * 28];

    int t = threadIdx.x;
    if (t < N * 4) sbx[t] = (int)floorf(boxes[b * N * 4 + t] * (float)FEAT);
    if (t < N) sconf[t] = confs[b * N + t];
    __syncthreads();

    // column masks for all 224 columns (threads t and t+128)
    for (int x = t; x < FEAT; x += 128) {
        unsigned cm = 0;
#pragma unroll
        for (int n = 0; n < N; n++) {
            int x1 = sbx[4 * n], x2 = sbx[4 * n + 2];
            cm |= (unsigned)(x >= x1 && x < x2) << n;
        }
        colm[x] = cm;
    }
    // row masks for this band's 32 pixel rows
    if (t < 32) {
        int y = r2 * 32 + t;
        unsigned rm = 0;
#pragma unroll
        for (int n = 0; n < N; n++) {
            int y1 = sbx[4 * n + 1], y2 = sbx[4 * n + 3];
            rm |= (unsigned)(y >= y1 && y < y2) << n;
        }
        rowm[t] = rm;
    }
    __syncthreads();

    if (t < 112) {
        int cy = t / 28, cx = t % 28;
        float tsum = 0.f;
#pragma unroll
        for (int ry = 0; ry < 8; ry++) {
            unsigned rm = rowm[cy * 8 + ry];
#pragma unroll
            for (int rx = 0; rx < 8; rx++) {
                unsigned m = rm & colm[cx * 8 + rx];
                float v = 0.f;
                while (m) {
                    int i = __ffs(m) - 1;
                    v += sconf[i];
                    m &= m - 1;
                }
                tsum += __fdividef(1.f, 1.f + __expf(-v));
            }
        }
        sum28[t] = tsum;
        g_att0[b * HW0 + (r2 * 4 + cy) * 28 + cx] = tsum * (1.f / 64.f);
    }
    __syncthreads();

    if (t < 28) {  // level 1: 2 rows x 14
        int ly = t / 14, lx = t % 14;
        float s = sum28[(2 * ly) * 28 + 2 * lx] + sum28[(2 * ly) * 28 + 2 * lx + 1] +
                  sum28[(2 * ly + 1) * 28 + 2 * lx] + sum28[(2 * ly + 1) * 28 + 2 * lx + 1];
        g_att1[b * HW1 + (r2 * 2 + ly) * 14 + lx] = s * (1.f / 256.f);
    }
    if (t < 7) {   // level 2: 1 row x 7
        float s = 0.f;
#pragma unroll
        for (int i = 0; i < 4; i++)
#pragma unroll
            for (int j = 0; j < 4; j++)
                s += sum28[i * 28 + 4 * t + j];
        g_att2[b * HW2 + r2 * 7 + t] = s * (1.f / 1024.f);
    }
}

// ---------------- K2: logits[l][b][c] = dot(feat[b,c,:], att[b,:]) ------
// grid = (C/8, B, 3), 256 threads = 8 warps; each warp does one c.
__global__ void logits_kernel(const float* __restrict__ f0,
                              const float* __restrict__ f1,
                              const float* __restrict__ f2) {
    int l = blockIdx.z, b = blockIdx.y;
    __shared__ __align__(16) float satt[HW0];

    int warp = threadIdx.x >> 5, lane = threadIdx.x & 31;
    int c = blockIdx.x * 8 + warp;
    float acc = 0.f;

    if (l == 0) {
        for (int i = threadIdx.x; i < HW0; i += 256) satt[i] = g_att0[b * HW0 + i];
        __syncthreads();
        const float4* fp = (const float4*)(f0 + ((size_t)(b * C + c)) * HW0);
        const float4* ap = (const float4*)satt;
#pragma unroll
        for (int k = 0; k < 7; k++) {
            int i = lane + 32 * k;
            if (i < HW0 / 4) {
                float4 v = fp[i], a = ap[i];
                acc = fmaf(v.x, a.x, acc);
                acc = fmaf(v.y, a.y, acc);
                acc = fmaf(v.z, a.z, acc);
                acc = fmaf(v.w, a.w, acc);
            }
        }
    } else if (l == 1) {
        for (int i = threadIdx.x; i < HW1; i += 256) satt[i] = g_att1[b * HW1 + i];
        __syncthreads();
        const float4* fp = (const float4*)(f1 + ((size_t)(b * C + c)) * HW1);
        const float4* ap = (const float4*)satt;
#pragma unroll
        for (int k = 0; k < 2; k++) {
            int i = lane + 32 * k;
            if (i < HW1 / 4) {
                float4 v = fp[i], a = ap[i];
                acc = fmaf(v.x, a.x, acc);
                acc = fmaf(v.y, a.y, acc);
                acc = fmaf(v.z, a.z, acc);
                acc = fmaf(v.w, a.w, acc);
            }
        }
    } else {
        for (int i = threadIdx.x; i < HW2; i += 256) satt[i] = g_att2[b * HW2 + i];
        __syncthreads();
        const float* fp = f2 + ((size_t)(b * C + c)) * HW2;
#pragma unroll
        for (int k = 0; k < 2; k++) {
            int i = lane + 32 * k;
            if (i < HW2) acc = fmaf(fp[i], satt[i], acc);
        }
    }

#pragma unroll
    for (int o = 16; o > 0; o >>= 1) acc += __shfl_xor_sync(0xffffffffu, acc, o);
    if (lane == 0) g_logits[(l * B + b) * C + c] = acc;
}

// -------- K3: fused softmax + scale. grid = (B*C/16, 3), 512 threads ------
// Each block: in-block softmax over the 512 logits of its (level,b), then
// 16 warps scale 16 channel rows.
__global__ void softscale_kernel(const float* __restrict__ f0,
                                 const float* __restrict__ f1,
                                 const float* __restrict__ f2,
                                 float* __restrict__ out) {
    int l = blockIdx.y;
    int b = blockIdx.x / (C / 16);
    int chunk = blockIdx.x % (C / 16);
    int t = threadIdx.x;
    int warp = t >> 5, lane = t & 31;

    __shared__ float red[16];
    __shared__ float smax, ssum;
    __shared__ float sw[16];

    // --- softmax over 512 logits (t == channel) ---
    float x = g_logits[(l * B + b) * C + t];
    float m = x;
#pragma unroll
    for (int o = 16; o > 0; o >>= 1) m = fmaxf(m, __shfl_xor_sync(0xffffffffu, m, o));
    if (lane == 0) red[warp] = m;
    __syncthreads();
    if (t == 0) {
        float mm = red[0];
#pragma unroll
        for (int i = 1; i < 16; i++) mm = fmaxf(mm, red[i]);
        smax = mm;
    }
    __syncthreads();
    float e = __expf(x - smax);
    float s = e;
#pragma unroll
    for (int o = 16; o > 0; o >>= 1) s += __shfl_xor_sync(0xffffffffu, s, o);
    if (lane == 0) red[warp] = s;
    __syncthreads();
    if (t == 0) {
        float ss = 0.f;
#pragma unroll
        for (int i = 0; i < 16; i++) ss += red[i];
        ssum = ss;
    }
    __syncthreads();
    if (t >= chunk * 16 && t < chunk * 16 + 16)
        sw[t - chunk * 16] = __fdividef(e, ssum);
    __syncthreads();

    // --- scale: warp w handles channel c = chunk*16 + w ---
    int c = chunk * 16 + warp;
    int row = b * C + c;
    float w = sw[warp];

    if (l == 0) {
        const float4* src = (const float4*)(f0 + (size_t)row * HW0);
        float4* dst = (float4*)(out + (size_t)b * OUT_ROW + (size_t)c * HW0);
#pragma unroll
        for (int k = 0; k < 7; k++) {
            int i = lane + 32 * k;
            if (i < HW0 / 4) {
                float4 v = src[i];
                v.x *= w; v.y *= w; v.z *= w; v.w *= w;
                dst[i] = v;
            }
        }
    } else if (l == 1) {
        const float4* src = (const float4*)(f1 + (size_t)row * HW1);
        float4* dst = (float4*)(out + (size_t)b * OUT_ROW + OUT_OFF1 + (size_t)c * HW1);
#pragma unroll
        for (int k = 0; k < 2; k++) {
            int i = lane + 32 * k;
            if (i < HW1 / 4) {
                float4 v = src[i];
                v.x *= w; v.y *= w; v.z *= w; v.w *= w;
                dst[i] = v;
            }
        }
    } else {
        const float* src = f2 + (size_t)row * HW2;
        float* dst = out + (size_t)b * OUT_ROW + OUT_OFF2 + (size_t)c * HW2;
#pragma unroll
        for (int k = 0; k < 2; k++) {
            int i = lane + 32 * k;
            if (i < HW2) dst[i] = src[i] * w;
        }
    }
}

extern "C" void kernel_launch(void* const* d_in, const int* in_sizes, int n_in,
                              void* d_out, int out_size) {
    const float* confs = (const float*)d_in[0];
    const float* boxes = (const float*)d_in[1];
    const float* f0 = (const float*)d_in[2];
    const float* f1 = (const float*)d_in[3];
    const float* f2 = (const float*)d_in[4];
    float* out = (float*)d_out;

    conf_att_kernel<<<dim3(7, B), 128>>>(confs, boxes);
    logits_kernel<<<dim3(C / 8, B, 3), 256>>>(f0, f1, f2);
    softscale_kernel<<<dim3(B * C / 16, 3), 512>>>(f0, f1, f2, out);
}

// round 4
// speedup vs baseline: 2.1204x; 1.9162x over previous
#include <cuda_runtime.h>
#include <math.h>

#define B 16
#define N 32
#define C 512
#define FEAT 224

#define HW0 784
#define HW1 196
#define HW2 49
#define OUT_ROW (C*(HW0+HW1+HW2))
#define OUT_OFF1 (C*HW0)         // 401408
#define OUT_OFF2 (C*(HW0+HW1))   // 501760
#define MAXSEG 96

// ---------------- scratch (no allocations allowed) ----------------
__device__ float    g_wx[B][MAXSEG];
__device__ unsigned g_colm[B][MAXSEG];
__device__ int      g_cellx[B][MAXSEG];
__device__ int      g_nsegx[B];
__device__ float    g_wy[B][MAXSEG];
__device__ unsigned g_rowm[B][MAXSEG];
__device__ int      g_bandidx[B][29];
__device__ float    g_sum28[B][HW0];   // per-8x8-tile sum of sigmoid
__device__ float    g_logits[3 * B * C];

// ---------------- K0: per-batch segment tables --------------------------
// Breakpoints = box edges U multiples of 8, so segments never straddle
// 8-wide pool cells / 8-tall pool bands.
__global__ void seg_kernel(const float* __restrict__ boxes) {
    int b = blockIdx.x;
    int t = threadIdx.x;
    __shared__ int sbx[N * 4];
    __shared__ unsigned char flag[FEAT];
    __shared__ int segstart[MAXSEG];
    __shared__ int woff[8];
    __shared__ int snseg;

    if (t < N * 4) sbx[t] = (int)floorf(boxes[b * N * 4 + t] * (float)FEAT);
    __syncthreads();

    for (int axis = 0; axis < 2; axis++) {
        if (t < FEAT) flag[t] = ((t & 7) == 0);
        __syncthreads();
        if (t < N) {
            int e1 = sbx[4 * t + axis];
            int e2 = sbx[4 * t + 2 + axis];
            if (e1 >= 0 && e1 < FEAT) flag[e1] = 1;
            if (e2 >= 0 && e2 < FEAT) flag[e2] = 1;
        }
        __syncthreads();

        unsigned bal = 0;
        int lane = t & 31, w = t >> 5;
        if (t < FEAT) {
            bal = __ballot_sync(0xffffffffu, flag[t] != 0);
            if (lane == 0) woff[w] = __popc(bal);
        }
        __syncthreads();
        if (t == 0) {
            int run = 0;
            for (int i = 0; i < 7; i++) { int c = woff[i]; woff[i] = run; run += c; }
            snseg = run;
        }
        __syncthreads();
        if (t < FEAT && flag[t]) {
            int idx = woff[w] + __popc(bal & ((1u << lane) - 1u));
            segstart[idx] = t;
        }
        __syncthreads();

        int nseg = snseg;
        if (t < nseg) {
            int s = segstart[t];
            int wd = ((t + 1 < nseg) ? segstart[t + 1] : FEAT) - s;
            unsigned m = 0;
#pragma unroll
            for (int n = 0; n < N; n++)
                m |= (unsigned)(s >= sbx[4 * n + axis] && s < sbx[4 * n + 2 + axis]) << n;
            if (axis == 0) {
                g_wx[b][t] = (float)wd;
                g_colm[b][t] = m;
                g_cellx[b][t] = s >> 3;
            } else {
                g_wy[b][t] = (float)wd;
                g_rowm[b][t] = m;
                if ((s & 7) == 0) g_bandidx[b][s >> 3] = t;
            }
        }
        if (t == 0) {
            if (axis == 0) g_nsegx[b] = nseg;
            else g_bandidx[b][28] = nseg;
        }
        __syncthreads();
    }
}

// ---------------- K1: rectangle eval -> 8x8 tile sums ------------------
// grid = (28 bands, B), 256 threads. Each rect (yseg, xseg): area * sigmoid(v).
__global__ void tile_kernel(const float* __restrict__ confs) {
    int band = blockIdx.x, b = blockIdx.y;
    int t = threadIdx.x;
    __shared__ float swx[MAXSEG];
    __shared__ unsigned scolm[MAXSEG];
    __shared__ int scell[MAXSEG];
    __shared__ float swy[72];
    __shared__ unsigned srowm[72];
    __shared__ float sconf[N];
    __shared__ float stile[28];
    __shared__ int snx, sny, si0;

    if (t < N) sconf[t] = confs[b * N + t];
    if (t == 0) {
        snx = g_nsegx[b];
        int i0 = g_bandidx[b][band];
        si0 = i0;
        sny = g_bandidx[b][band + 1] - i0;
    }
    if (t < 28) stile[t] = 0.f;
    __syncthreads();

    int nx = snx, ny = sny, i0 = si0;
    for (int i = t; i < nx; i += 256) {
        swx[i] = g_wx[b][i];
        scolm[i] = g_colm[b][i];
        scell[i] = g_cellx[b][i];
    }
    for (int i = t; i < ny; i += 256) {
        swy[i] = g_wy[b][i0 + i];
        srowm[i] = g_rowm[b][i0 + i];
    }
    __syncthreads();

    int pairs = nx * ny;
    for (int p = t; p < pairs; p += 256) {
        int ys = p / nx, xs = p - ys * nx;
        unsigned m = srowm[ys] & scolm[xs];
        float v = 0.f;
        while (m) {
            int i = __ffs(m) - 1;
            v += sconf[i];
            m &= m - 1;
        }
        float sg = __fdividef(1.f, 1.f + __expf(-v));
        atomicAdd(&stile[scell[xs]], swy[ys] * swx[xs] * sg);
    }
    __syncthreads();
    if (t < 28) g_sum28[b][band * 28 + t] = stile[t];
}

// ---------------- K2: logits[l][b][c] = dot(feat[b,c,:], att[b,:]) ------
// grid = (C/8, B, 3), 256 threads = 8 warps; builds att from tile sums.
__global__ void logits_kernel(const float* __restrict__ f0,
                              const float* __restrict__ f1,
                              const float* __restrict__ f2) {
    int l = blockIdx.z, b = blockIdx.y;
    __shared__ __align__(16) float satt[HW0];

    int warp = threadIdx.x >> 5, lane = threadIdx.x & 31;
    int c = blockIdx.x * 8 + warp;
    int t = threadIdx.x;
    float acc = 0.f;
    const float* gs = g_sum28[b];

    if (l == 0) {
        for (int i = t; i < HW0; i += 256) satt[i] = gs[i] * (1.f / 64.f);
        __syncthreads();
        const float4* fp = (const float4*)(f0 + ((size_t)(b * C + c)) * HW0);
        const float4* ap = (const float4*)satt;
#pragma unroll
        for (int k = 0; k < 7; k++) {
            int i = lane + 32 * k;
            if (i < HW0 / 4) {
                float4 v = fp[i], a = ap[i];
                acc = fmaf(v.x, a.x, acc);
                acc = fmaf(v.y, a.y, acc);
                acc = fmaf(v.z, a.z, acc);
                acc = fmaf(v.w, a.w, acc);
            }
        }
    } else if (l == 1) {
        if (t < HW1) {
            int ay = t / 14, ax = t % 14;
            int base = (2 * ay) * 28 + 2 * ax;
            float s = gs[base] + gs[base + 1] + gs[base + 28] + gs[base + 29];
            satt[t] = s * (1.f / 256.f);
        }
        __syncthreads();
        const float4* fp = (const float4*)(f1 + ((size_t)(b * C + c)) * HW1);
        const float4* ap = (const float4*)satt;
#pragma unroll
        for (int k = 0; k < 2; k++) {
            int i = lane + 32 * k;
            if (i < HW1 / 4) {
                float4 v = fp[i], a = ap[i];
                acc = fmaf(v.x, a.x, acc);
                acc = fmaf(v.y, a.y, acc);
                acc = fmaf(v.z, a.z, acc);
                acc = fmaf(v.w, a.w, acc);
            }
        }
    } else {
        if (t < HW2) {
            int ay = t / 7, ax = t % 7;
            float s = 0.f;
#pragma unroll
            for (int iy = 0; iy < 4; iy++)
#pragma unroll
                for (int ix = 0; ix < 4; ix++)
                    s += gs[(4 * ay + iy) * 28 + 4 * ax + ix];
            satt[t] = s * (1.f / 1024.f);
        }
        __syncthreads();
        const float* fp = f2 + ((size_t)(b * C + c)) * HW2;
#pragma unroll
        for (int k = 0; k < 2; k++) {
            int i = lane + 32 * k;
            if (i < HW2) acc = fmaf(fp[i], satt[i], acc);
        }
    }

#pragma unroll
    for (int o = 16; o > 0; o >>= 1) acc += __shfl_xor_sync(0xffffffffu, acc, o);
    if (lane == 0) g_logits[(l * B + b) * C + c] = acc;
}

// -------- K3: fused softmax + scale. grid = (B*C/16, 3), 512 threads ------
__global__ void softscale_kernel(const float* __restrict__ f0,
                                 const float* __restrict__ f1,
                                 const float* __restrict__ f2,
                                 float* __restrict__ out) {
    int l = blockIdx.y;
    int b = blockIdx.x / (C / 16);
    int chunk = blockIdx.x % (C / 16);
    int t = threadIdx.x;
    int warp = t >> 5, lane = t & 31;

    __shared__ float red[16];
    __shared__ float smax, ssum;
    __shared__ float sw[16];

    float x = g_logits[(l * B + b) * C + t];
    float m = x;
#pragma unroll
    for (int o = 16; o > 0; o >>= 1) m = fmaxf(m, __shfl_xor_sync(0xffffffffu, m, o));
    if (lane == 0) red[warp] = m;
    __syncthreads();
    if (t == 0) {
        float mm = red[0];
#pragma unroll
        for (int i = 1; i < 16; i++) mm = fmaxf(mm, red[i]);
        smax = mm;
    }
    __syncthreads();
    float e = __expf(x - smax);
    float s = e;
#pragma unroll
    for (int o = 16; o > 0; o >>= 1) s += __shfl_xor_sync(0xffffffffu, s, o);
    if (lane == 0) red[warp] = s;
    __syncthreads();
    if (t == 0) {
        float ss = 0.f;
#pragma unroll
        for (int i = 0; i < 16; i++) ss += red[i];
        ssum = ss;
    }
    __syncthreads();
    if (t >= chunk * 16 && t < chunk * 16 + 16)
        sw[t - chunk * 16] = __fdividef(e, ssum);
    __syncthreads();

    int c = chunk * 16 + warp;
    int row = b * C + c;
    float w = sw[warp];

    if (l == 0) {
        const float4* src = (const float4*)(f0 + (size_t)row * HW0);
        float4* dst = (float4*)(out + (size_t)b * OUT_ROW + (size_t)c * HW0);
#pragma unroll
        for (int k = 0; k < 7; k++) {
            int i = lane + 32 * k;
            if (i < HW0 / 4) {
                float4 v = src[i];
                v.x *= w; v.y *= w; v.z *= w; v.w *= w;
                dst[i] = v;
            }
        }
    } else if (l == 1) {
        const float4* src = (const float4*)(f1 + (size_t)row * HW1);
        float4* dst = (float4*)(out + (size_t)b * OUT_ROW + OUT_OFF1 + (size_t)c * HW1);
#pragma unroll
        for (int k = 0; k < 2; k++) {
            int i = lane + 32 * k;
            if (i < HW1 / 4) {
                float4 v = src[i];
                v.x *= w; v.y *= w; v.z *= w; v.w *= w;
                dst[i] = v;
            }
        }
    } else {
        const float* src = f2 + (size_t)row * HW2;
        float* dst = out + (size_t)b * OUT_ROW + OUT_OFF2 + (size_t)c * HW2;
#pragma unroll
        for (int k = 0; k < 2; k++) {
            int i = lane + 32 * k;
            if (i < HW2) dst[i] = src[i] * w;
        }
    }
}

extern "C" void kernel_launch(void* const* d_in, const int* in_sizes, int n_in,
                              void* d_out, int out_size) {
    const float* confs = (const float*)d_in[0];
    const float* boxes = (const float*)d_in[1];
    const float* f0 = (const float*)d_in[2];
    const float* f1 = (const float*)d_in[3];
    const float* f2 = (const float*)d_in[4];
    float* out = (float*)d_out;

    seg_kernel<<<B, 256>>>(boxes);
    tile_kernel<<<dim3(28, B), 256>>>(confs);
    logits_kernel<<<dim3(C / 8, B, 3), 256>>>(f0, f1, f2);
    softscale_kernel<<<dim3(B * C / 16, 3), 512>>>(f0, f1, f2, out);
}